// round 1
// baseline (speedup 1.0000x reference)
#include <cuda_runtime.h>
#include <math.h>

#define T_STEPS 128
#define BATCH   128
#define SAMP    8
#define DIN     64
#define RDIM    256
#define ZDIM    128
#define HDIM    512
#define BS      1024   /* BATCH*SAMP */
#define TB      16384  /* T_STEPS*BATCH */

#define DT       0.05f
#define SQRT_DT  0.22360679774997896f
#define LOG_2PI  1.8378770664093453f

// ---------------- scratch (static device globals; no runtime alloc) -------
__device__ __align__(16) float g_Hh[TB * HDIM];     // h @ Wd1[:R] + bd1       [T,B,H]
__device__ __align__(16) float g_Hhpos[TB * HDIM];  // (h+hpos)@Wd1[:R] + bd1  [T,B,H]
__device__ __align__(16) float g_Hph[TB * HDIM];    // h @ Wp1[:R] + bp1       [T,B,H]
__device__ __align__(16) float g_Hf[TB * HDIM];     // relu(h@Wf1+bf1)         [T,B,H]
__device__ __align__(16) float g_diff[TB * ZDIM];   // exp(Hf@Wf2+bf2)         [T,B,Z]
__device__ __align__(16) float g_Mt[T_STEPS * BATCH];
__device__ __align__(16) float g_z[BS * ZDIM];      // state z [B*S, Z]
__device__ __align__(16) float g_Hz[BS * HDIM];     // z @ Wd1[R:,:]
__device__ __align__(16) float g_Hpz[BS * HDIM];    // z @ Wp1[R:,:]
__device__ __align__(16) float g_UV[2 * BS * ZDIM]; // [prior(1024); poster(1024)] x Z
__device__ __align__(16) float g_P[BS * ZDIM];      // p preact [B*S, 2*Din]
__device__ float g_kldpart[T_STEPS * 128];
__device__ float g_reconpart[T_STEPS * 64];

// ---------------- z0: cov -> CH -> Z (relu, tanh) --------------------------
__global__ void z0_kernel(const float* __restrict__ cov,
                          const float* __restrict__ Wc1, const float* __restrict__ bc1,
                          const float* __restrict__ Wc2, const float* __restrict__ bc2)
{
    int b = blockIdx.x;     // 128 blocks
    int tid = threadIdx.x;  // 128 threads
    __shared__ float sc[32];
    __shared__ float sh[64];
    if (tid < 32) sc[tid] = cov[b * 32 + tid];
    __syncthreads();
    if (tid < 64) {
        float acc = bc1[tid];
        #pragma unroll
        for (int c = 0; c < 32; c++) acc = fmaf(sc[c], Wc1[c * 64 + tid], acc);
        sh[tid] = fmaxf(acc, 0.f);
    }
    __syncthreads();
    float acc = bc2[tid];
    #pragma unroll
    for (int k = 0; k < 64; k++) acc = fmaf(sh[k], Wc2[k * 128 + tid], acc);
    float z = tanhf(acc);
    #pragma unroll
    for (int s = 0; s < SAMP; s++)
        g_z[(b * SAMP + s) * ZDIM + tid] = z;
}

// ---------------- Mt = mean(M, axis=-1) ------------------------------------
__global__ void mt_kernel(const float* __restrict__ M)
{
    int i = blockIdx.x * blockDim.x + threadIdx.x;   // 16384 rows
    const float4* p = (const float4*)(M + (size_t)i * DIN);
    float s = 0.f;
    #pragma unroll
    for (int j = 0; j < DIN / 4; j++) { float4 v = p[j]; s += v.x + v.y + v.z + v.w; }
    g_Mt[i] = s * (1.f / (float)DIN);
}

// ---------------- generic fp32 tiled GEMM: C = act(A@W + bias) -------------
// A:[M,K] ld=K, W:[K,N] ld=N, C:[M,N] ld=N.  ACT: 0 none, 1 relu, 2 exp.
// SUMA: A := A + A2 elementwise. All dims multiples of 64 (K mult of 32).
template<int ACT, bool SUMA>
__global__ void gemm_f32(const float* __restrict__ A, const float* __restrict__ A2,
                         const float* __restrict__ W, const float* __restrict__ bias,
                         float* __restrict__ C, int M, int N, int K)
{
    __shared__ float sA[64][33];
    __shared__ float sB[32][68];
    const int bm = blockIdx.y * 64;
    const int bn = blockIdx.x * 64;
    const int tid = threadIdx.x;       // 256
    const int tx = tid & 15;
    const int ty = tid >> 4;
    float acc[4][4] = {};
    for (int k0 = 0; k0 < K; k0 += 32) {
        #pragma unroll
        for (int l = 0; l < 2; l++) {
            int v  = tid + l * 256;       // 0..511
            int r  = v >> 3;
            int c4 = (v & 7) * 4;
            float4 av = *(const float4*)&A[(size_t)(bm + r) * K + k0 + c4];
            if (SUMA) {
                float4 b4 = *(const float4*)&A2[(size_t)(bm + r) * K + k0 + c4];
                av.x += b4.x; av.y += b4.y; av.z += b4.z; av.w += b4.w;
            }
            sA[r][c4 + 0] = av.x; sA[r][c4 + 1] = av.y;
            sA[r][c4 + 2] = av.z; sA[r][c4 + 3] = av.w;
        }
        #pragma unroll
        for (int l = 0; l < 2; l++) {
            int v  = tid + l * 256;
            int r  = v >> 4;              // 0..31
            int c4 = (v & 15) * 4;
            *(float4*)&sB[r][c4] = *(const float4*)&W[(size_t)(k0 + r) * N + bn + c4];
        }
        __syncthreads();
        #pragma unroll
        for (int k = 0; k < 32; k++) {
            float a[4];
            #pragma unroll
            for (int i = 0; i < 4; i++) a[i] = sA[ty * 4 + i][k];
            float4 bv = *(const float4*)&sB[k][tx * 4];
            float b[4] = { bv.x, bv.y, bv.z, bv.w };
            #pragma unroll
            for (int i = 0; i < 4; i++)
                #pragma unroll
                for (int j = 0; j < 4; j++)
                    acc[i][j] = fmaf(a[i], b[j], acc[i][j]);
        }
        __syncthreads();
    }
    #pragma unroll
    for (int i = 0; i < 4; i++) {
        int r = bm + ty * 4 + i;
        #pragma unroll
        for (int j = 0; j < 4; j++) {
            int c = bn + tx * 4 + j;
            float v = acc[i][j] + (bias ? bias[c] : 0.f);
            if (ACT == 1) v = fmaxf(v, 0.f);
            if (ACT == 2) v = expf(v);
            C[(size_t)r * N + c] = v;
        }
    }
}

// ---------------- head GEMMs with fused A construction ---------------------
// MODE 0: drift. Virtual A [2048,512]: rows 0..1023 = relu(Hh[t]+Hz),
//         rows 1024..2047 = relu(Hhpos[t]+Hz). C = 0.1*tanh(A@Wd2+bd2) -> g_UV.
// MODE 1: p. A [1024,512] = relu(Hph[t]+Hpz). C = A@Wp2+bp2 -> g_P.
// Tile: BM=64, BN=32, BK=32, 256 threads, each thread 2x4 outputs.
template<int MODE>
__global__ void gemm_head(int t, const float* __restrict__ W,
                          const float* __restrict__ bias)
{
    __shared__ float sA[64][33];
    __shared__ float sB[32][36];
    const int bm = blockIdx.y * 64;
    const int bn = blockIdx.x * 32;
    const int tid = threadIdx.x;   // 256
    const int tx = tid & 7;        // 8 col groups of 4
    const int ty = tid >> 3;       // 32 row groups of 2
    float acc[2][4] = {};
    const float* __restrict__ Hsrc;
    int rbase;
    if (MODE == 0) {
        Hsrc  = (bm < 1024) ? g_Hh : g_Hhpos;
        rbase = (bm < 1024) ? bm : (bm - 1024);
    } else {
        Hsrc  = g_Hph;
        rbase = bm;
    }
    const float* __restrict__ Zsrc = (MODE == 0) ? g_Hz : g_Hpz;

    for (int k0 = 0; k0 < HDIM; k0 += 32) {
        #pragma unroll
        for (int l = 0; l < 2; l++) {
            int v  = tid + l * 256;
            int r  = v >> 3;
            int c4 = (v & 7) * 4;
            int rr = rbase + r;          // row in [0,1024)
            int b  = rr >> 3;
            float4 h4 = *(const float4*)&Hsrc[((size_t)(t * BATCH + b)) * HDIM + k0 + c4];
            float4 z4 = *(const float4*)&Zsrc[(size_t)rr * HDIM + k0 + c4];
            sA[r][c4 + 0] = fmaxf(h4.x + z4.x, 0.f);
            sA[r][c4 + 1] = fmaxf(h4.y + z4.y, 0.f);
            sA[r][c4 + 2] = fmaxf(h4.z + z4.z, 0.f);
            sA[r][c4 + 3] = fmaxf(h4.w + z4.w, 0.f);
        }
        {
            int r  = tid >> 3;
            int c4 = (tid & 7) * 4;
            *(float4*)&sB[r][c4] = *(const float4*)&W[(size_t)(k0 + r) * ZDIM + bn + c4];
        }
        __syncthreads();
        #pragma unroll
        for (int k = 0; k < 32; k++) {
            float a0 = sA[ty * 2 + 0][k];
            float a1 = sA[ty * 2 + 1][k];
            float4 bv = *(const float4*)&sB[k][tx * 4];
            acc[0][0] = fmaf(a0, bv.x, acc[0][0]);
            acc[0][1] = fmaf(a0, bv.y, acc[0][1]);
            acc[0][2] = fmaf(a0, bv.z, acc[0][2]);
            acc[0][3] = fmaf(a0, bv.w, acc[0][3]);
            acc[1][0] = fmaf(a1, bv.x, acc[1][0]);
            acc[1][1] = fmaf(a1, bv.y, acc[1][1]);
            acc[1][2] = fmaf(a1, bv.z, acc[1][2]);
            acc[1][3] = fmaf(a1, bv.w, acc[1][3]);
        }
        __syncthreads();
    }
    #pragma unroll
    for (int i = 0; i < 2; i++) {
        int r = bm + ty * 2 + i;         // global row (0..2047 for MODE 0)
        #pragma unroll
        for (int j = 0; j < 4; j++) {
            int c = bn + tx * 4 + j;
            float v = acc[i][j] + bias[c];
            if (MODE == 0) g_UV[(size_t)r * ZDIM + c] = 0.1f * tanhf(v);
            else           g_P[(size_t)r * ZDIM + c]  = v;
        }
    }
}

// ---------------- z update + KLD partial (deterministic slots) -------------
__global__ void step_update(int t, const float* __restrict__ noise)
{
    const int blk = blockIdx.x;   // 128
    const int tid = threadIdx.x;  // 256
    float local = 0.f;
    #pragma unroll
    for (int l = 0; l < 4; l++) {
        int e   = blk * 1024 + l * 256 + tid;   // 0..131071
        int row = e >> 7;                       // b*8+s
        int col = e & 127;
        int b   = row >> 3;
        int s   = row & 7;
        float prior  = g_UV[e];
        float poster = g_UV[BS * ZDIM + e];
        float d   = g_diff[((size_t)(t * BATCH + b)) * ZDIM + col];
        float eps = noise[(((size_t)(t * BATCH + b)) * SAMP + s) * ZDIM + col];
        float z = g_z[e] + DT * poster + SQRT_DT * d * eps;
        g_z[e] = z;
        float err = (prior - poster) / d;
        local = fmaf(err, err, local);
    }
    __shared__ float red[256];
    red[tid] = local;
    __syncthreads();
    for (int s2 = 128; s2 > 0; s2 >>= 1) {
        if (tid < s2) red[tid] += red[tid + s2];
        __syncthreads();
    }
    if (tid == 0) g_kldpart[t * 128 + blk] = red[0];
}

// ---------------- NLL / recon partial ---------------------------------------
__global__ void step_recon(int t, const float* __restrict__ X)
{
    const int blk = blockIdx.x;   // 64
    const int tid = threadIdx.x;  // 256
    float local = 0.f;
    #pragma unroll
    for (int l = 0; l < 4; l++) {
        int e    = blk * 1024 + l * 256 + tid;  // 0..65535
        int row  = e >> 6;                      // 0..1023
        int dcol = e & 63;
        int b    = row >> 3;
        float mean   = g_P[row * ZDIM + dcol];
        float logvar = g_P[row * ZDIM + dcol + 64];
        float x  = X[((size_t)(t * BATCH + b)) * DIN + dcol];
        float dv = x - mean;
        float nll = 0.5f * (LOG_2PI + logvar + dv * dv * expf(-logvar));
        local = fmaf(g_Mt[t * BATCH + b], nll, local);
    }
    __shared__ float red[256];
    red[tid] = local;
    __syncthreads();
    for (int s2 = 128; s2 > 0; s2 >>= 1) {
        if (tid < s2) red[tid] += red[tid + s2];
        __syncthreads();
    }
    if (tid == 0) g_reconpart[t * 64 + blk] = red[0];
}

// ---------------- final fixed-order reduction + output ---------------------
__global__ void copy_z(float* __restrict__ out)
{
    int i = blockIdx.x * blockDim.x + threadIdx.x;
    out[i] = g_z[i];
}

__global__ void finalize(float* __restrict__ out, int out_size)
{
    int tid = threadIdx.x;   // 256
    float k = 0.f, r = 0.f;
    for (int i = tid; i < T_STEPS * 128; i += 256) k += g_kldpart[i];
    for (int i = tid; i < T_STEPS * 64;  i += 256) r += g_reconpart[i];
    __shared__ float rk[256], rr[256];
    rk[tid] = k; rr[tid] = r;
    __syncthreads();
    for (int s = 128; s > 0; s >>= 1) {
        if (tid < s) { rk[tid] += rk[tid + s]; rr[tid] += rr[tid + s]; }
        __syncthreads();
    }
    if (tid == 0) {
        float kld   = rk[0] * (0.5f * DT / (float)BS);
        float recon = rr[0] * (1.f / (float)BS);
        out[out_size - 3] = recon + kld;  // loss_total (LAMBDA=1)
        out[out_size - 2] = recon;        // loss_recon
        out[out_size - 1] = kld;          // loss_kld
    }
}

// ---------------- launch ----------------------------------------------------
extern "C" void kernel_launch(void* const* d_in, const int* in_sizes, int n_in,
                              void* d_out, int out_size)
{
    const float* X     = (const float*)d_in[0];
    const float* M     = (const float*)d_in[1];
    const float* cov   = (const float*)d_in[2];
    const float* ph    = (const float*)d_in[3];
    const float* phpos = (const float*)d_in[4];
    const float* noise = (const float*)d_in[5];
    const float* Wc1 = (const float*)d_in[6],  *bc1 = (const float*)d_in[7];
    const float* Wc2 = (const float*)d_in[8],  *bc2 = (const float*)d_in[9];
    const float* Wd1 = (const float*)d_in[10], *bd1 = (const float*)d_in[11];
    const float* Wd2 = (const float*)d_in[12], *bd2 = (const float*)d_in[13];
    const float* Wf1 = (const float*)d_in[14], *bf1 = (const float*)d_in[15];
    const float* Wf2 = (const float*)d_in[16], *bf2 = (const float*)d_in[17];
    const float* Wp1 = (const float*)d_in[18], *bp1 = (const float*)d_in[19];
    const float* Wp2 = (const float*)d_in[20], *bp2 = (const float*)d_in[21];
    float* out = (float*)d_out;

    float *pHh, *pHhpos, *pHph, *pHf, *pdiff, *pz, *pHz, *pHpz;
    cudaGetSymbolAddress((void**)&pHh,    g_Hh);
    cudaGetSymbolAddress((void**)&pHhpos, g_Hhpos);
    cudaGetSymbolAddress((void**)&pHph,   g_Hph);
    cudaGetSymbolAddress((void**)&pHf,    g_Hf);
    cudaGetSymbolAddress((void**)&pdiff,  g_diff);
    cudaGetSymbolAddress((void**)&pz,     g_z);
    cudaGetSymbolAddress((void**)&pHz,    g_Hz);
    cudaGetSymbolAddress((void**)&pHpz,   g_Hpz);

    // ---- precompute (parallel over all T) ----
    z0_kernel<<<BATCH, 128>>>(cov, Wc1, bc1, Wc2, bc2);
    mt_kernel<<<64, 256>>>(M);
    gemm_f32<0, false><<<dim3(HDIM/64, TB/64), 256>>>(ph,    nullptr, Wd1, bd1, pHh,    TB, HDIM, RDIM);
    gemm_f32<0, true ><<<dim3(HDIM/64, TB/64), 256>>>(ph,    phpos,   Wd1, bd1, pHhpos, TB, HDIM, RDIM);
    gemm_f32<0, false><<<dim3(HDIM/64, TB/64), 256>>>(ph,    nullptr, Wp1, bp1, pHph,   TB, HDIM, RDIM);
    gemm_f32<1, false><<<dim3(HDIM/64, TB/64), 256>>>(ph,    nullptr, Wf1, bf1, pHf,    TB, HDIM, RDIM);
    gemm_f32<2, false><<<dim3(ZDIM/64, TB/64), 256>>>(pHf,   nullptr, Wf2, bf2, pdiff,  TB, ZDIM, HDIM);

    // ---- sequential scan ----
    for (int t = 0; t < T_STEPS; t++) {
        gemm_f32<0, false><<<dim3(HDIM/64, BS/64), 256>>>(pz, nullptr, Wd1 + RDIM * HDIM,
                                                          nullptr, pHz, BS, HDIM, ZDIM);
        gemm_head<0><<<dim3(ZDIM/32, 2 * BS / 64), 256>>>(t, Wd2, bd2);
        step_update<<<128, 256>>>(t, noise);
        gemm_f32<0, false><<<dim3(HDIM/64, BS/64), 256>>>(pz, nullptr, Wp1 + RDIM * HDIM,
                                                          nullptr, pHpz, BS, HDIM, ZDIM);
        gemm_head<1><<<dim3(ZDIM/32, BS / 64), 256>>>(t, Wp2, bp2);
        step_recon<<<64, 256>>>(t, X);
    }

    // ---- outputs ----
    copy_z<<<(BS * ZDIM) / 256, 256>>>(out);
    finalize<<<1, 256>>>(out, out_size);
}